// round 6
// baseline (speedup 1.0000x reference)
#include <cuda_runtime.h>

#define L 256
#define BB 16
#define LL2 (L * L)
#define NEGF (-1000000000.0f)
#define NCHART BB
#define NBCE 32
#define NCTA (NCHART + NBCE)
#define TMAIN 512
#define NW (TMAIN / 32)
#define TRI ((L * (L + 1)) / 2)          // 32896 floats
#define SMEM_BYTES (TRI * 4)             // 131584 B

// -------- device scratch (no allocations allowed) --------
__device__ float  g_bS[BB * LL2];   // beta start-major: bS[i*L + w] = beta(i, i+w)
__device__ float  g_gS[BB * LL2];   // gamma=alpha+lg start-major
__device__ float  g_gE[BB * LL2];   // gamma end-major: gE[j*L + w] = gamma(j-w, j)
__device__ int    g_lens[BB];
__device__ double g_span[BB];
__device__ double g_bce1[NBCE], g_bce2[NBCE];
__device__ unsigned long long g_ctr;

__device__ __forceinline__ int roffE(int j) { return (j * (j + 1)) >> 1; }

// two-phase warp LSE over T terms; f(t) -> value; returns m+log(sum) in lane 0
template<int NCH, class F>
__device__ __forceinline__ float warp_lse(int T, int lane, F f) {
    float vv[NCH];
    float m = NEGF;
    #pragma unroll
    for (int k = 0; k < NCH; ++k) {
        int t = lane + k * 32;
        vv[k] = (t < T) ? f(t) : NEGF;
        m = fmaxf(m, vv[k]);
    }
    #pragma unroll
    for (int o = 16; o; o >>= 1) m = fmaxf(m, __shfl_xor_sync(0xffffffffu, m, o));
    float s = 0.f;
    #pragma unroll
    for (int k = 0; k < NCH; ++k) s += __expf(vv[k] - m);   // NEGF terms underflow to 0
    #pragma unroll
    for (int o = 16; o; o >>= 1) s += __shfl_xor_sync(0xffffffffu, s, o);
    return m + __logf(s);
}

// dtype-robust length scan (one warp, result in all lanes)
__device__ __forceinline__ int robust_len(const unsigned char* __restrict__ maskspan,
                                          int b, int lane) {
    const unsigned char* rowb = maskspan + (size_t)b * LL2;
    int c8 = 0;
    for (int j = lane; j < L; j += 32) c8 += (rowb[j] != 0) ? 1 : 0;
    #pragma unroll
    for (int o = 16; o; o >>= 1) c8 += __shfl_xor_sync(0xffffffffu, c8, o);
    int n;
    if (c8 >= 100 && rowb[0] == 1) {
        n = c8;
    } else {
        const unsigned int* rowi = ((const unsigned int*)maskspan) + (size_t)b * LL2;
        int c32 = 0;
        for (int j = lane; j < L; j += 32) c32 += (rowi[j] != 0u) ? 1 : 0;
        #pragma unroll
        for (int o = 16; o; o >>= 1) c32 += __shfl_xor_sync(0xffffffffu, c32, o);
        n = c32;
    }
    return max(1, min(L, n));
}

__global__ void __launch_bounds__(TMAIN, 1)
main_kernel(const float* __restrict__ lg_all,
            const float* __restrict__ ph_all,  const float* __restrict__ pt_all,
            const float* __restrict__ pharc_all,
            const int* __restrict__ spans_all,
            const int* __restrict__ phind_all, const int* __restrict__ ptind_all,
            const unsigned char* __restrict__ maskspan,
            float* __restrict__ out) {
    extern __shared__ float sE[];          // beta end-major triangular chart (smem)
    __shared__ double sh_red[NW];
    __shared__ int    sh_n;
    __shared__ int    sh_lens[BB];

    const int cb   = blockIdx.x;
    const int tid  = threadIdx.x;
    const int lane = tid & 31;
    const int wid  = tid >> 5;

    if (cb < NCHART) {
        // ============ chart CTA: inside + outside + span loss for batch cb ============
        const int b = cb;
        if (wid == 0) {
            int n = robust_len(maskspan, b, lane);
            if (lane == 0) { sh_n = n; g_lens[b] = n; }
        }
        __syncthreads();
        const int n = sh_n;

        const float* __restrict__ lg    = lg_all    + (size_t)b * LL2;
        const float* __restrict__ pharc = pharc_all + (size_t)b * LL2;
        const int*   __restrict__ spans = spans_all + (size_t)b * LL2;
        float* __restrict__ bS = g_bS + (size_t)b * LL2;
        float* __restrict__ gS = g_gS + (size_t)b * LL2;
        float* __restrict__ gE = g_gE + (size_t)b * LL2;

        // width 0
        for (int i = tid; i < n; i += TMAIN) {
            float v = __ldg(&lg[i * L + i]);
            sE[roffE(i)] = v;
            bS[i * L]    = v;
        }
        __syncthreads();

        // ---- inside, widths 1..n-1 ----
        for (int w = 1; w < n; ++w) {
            const int ncells = n - w;
            if (w <= 8) {
                // thread per cell, register-cached two-phase
                for (int i = tid; i < ncells; i += TMAIN) {
                    const float* __restrict__ Lr = bS + i * L;
                    const float* __restrict__ sR = sE + roffE(i + w);
                    float vv[8]; float m = NEGF;
                    #pragma unroll
                    for (int k = 0; k < 8; ++k) {
                        if (k < w) { vv[k] = __ldg(Lr + k) + sR[w - 1 - k]; m = fmaxf(m, vv[k]); }
                    }
                    float s = 0.f;
                    #pragma unroll
                    for (int k = 0; k < 8; ++k) if (k < w) s += __expf(vv[k] - m);
                    float res = m + __logf(s) + __ldg(&lg[i * L + i + w]);
                    sE[roffE(i + w) + w] = res;
                    bS[i * L + w]        = res;
                }
            } else {
                for (int i = wid; i < ncells; i += NW) {
                    const float* __restrict__ Lr = bS + i * L;
                    const float* __restrict__ sR = sE + roffE(i + w) + (w - 1);
                    auto f = [&](int t) { return __ldg(Lr + t) + sR[-t]; };
                    float v;
                    if      (w <= 32)  v = warp_lse<1>(w, lane, f);
                    else if (w <= 128) v = warp_lse<4>(w, lane, f);
                    else               v = warp_lse<8>(w, lane, f);
                    if (lane == 0) {
                        float res = v + __ldg(&lg[i * L + i + w]);
                        sE[roffE(i + w) + w] = res;
                        bS[i * L + w]        = res;
                    }
                }
            }
            __syncthreads();
        }

        const float logZ = sE[roffE(n - 1) + (n - 1)];
        double acc = 0.0;

        // ---- outside root (a=0, w=n-1): alpha=0 ----
        if (tid == 0) {
            float lgv = __ldg(&lg[0 * L + (n - 1)]);
            gS[0 * L + (n - 1)]       = lgv;   // gamma = 0 + lg
            gE[(n - 1) * L + (n - 1)] = lgv;
            float p  = 1.f / (1.f + __expf(-__ldg(&pharc[n - 1])));
            float pm = p * 1.0f;               // mu(root) = 1
            acc += (__ldg(&spans[n - 1]) >= 2) ? (double)__logf(pm) : (double)log1pf(-pm);
        }
        __syncthreads();

        // ---- outside, widths n-2..0 (loss fused) ----
        for (int w = n - 2; w >= 0; --w) {
            const int ncells = n - w;
            const int T0 = n - 1 - w;     // T for every cell at this level
            for (int a = wid; a < ncells; a += NW) {
                const int bj = a + w;
                const int c1 = n - 1 - bj;
                const float* __restrict__ gSr = gS + a * L + (w + 1);       // [t]
                const float* __restrict__ bSr = bS + (bj + 1) * L;          // [t]
                const float* __restrict__ gEr = gE + bj * L + bj;           // [-ii]
                const float* __restrict__ sB2 = sE + roffE(a - 1) + (a - 1);// [-ii]
                auto f = [&](int t) {
                    if (t < c1) return __ldg(gSr + t) + __ldg(bSr + t);
                    int ii = t - c1;
                    return __ldg(gEr - ii) + sB2[-ii];
                };
                float al;
                if      (T0 <= 32)  al = warp_lse<1>(T0, lane, f);
                else if (T0 <= 128) al = warp_lse<4>(T0, lane, f);
                else                al = warp_lse<8>(T0, lane, f);
                if (lane == 0) {
                    float lgv = __ldg(&lg[a * L + bj]);
                    gS[a * L + w]  = al + lgv;
                    gE[bj * L + w] = al + lgv;
                    float mu = fminf(__expf(al + sE[roffE(bj) + w] - logZ), 1.0f);
                    float p  = 1.f / (1.f + __expf(-__ldg(&pharc[a * L + bj])));
                    float pm = p * mu;
                    acc += (__ldg(&spans[a * L + bj]) >= 2) ? (double)__logf(pm)
                                                            : (double)log1pf(-pm);
                }
            }
            __syncthreads();
        }

        // reduce span loss -> g_span[b]
        #pragma unroll
        for (int o = 16; o; o >>= 1) acc += __shfl_down_sync(0xffffffffu, acc, o);
        if (lane == 0) sh_red[wid] = acc;
        __syncthreads();
        if (wid == 0) {
            double v = (lane < NW) ? sh_red[lane] : 0.0;
            #pragma unroll
            for (int o = 8; o; o >>= 1) v += __shfl_down_sync(0xffffffffu, v, o);
            if (lane == 0) g_span[b] = v;
        }
        __syncthreads();
    } else {
        // ================= BCE CTA =================
        const int c = cb - NCHART;
        if (wid < BB) {
            int nn = robust_len(maskspan, wid, lane);
            if (lane == 0) sh_lens[wid] = nn;
        }
        __syncthreads();

        float f1 = 0.f, f2 = 0.f;
        const size_t total = (size_t)BB * LL2;
        for (size_t idx = (size_t)c * TMAIN + tid; idx < total; idx += (size_t)NBCE * TMAIN) {
            int bb = (int)(idx >> 16);
            int i  = (int)((idx >> 8) & (L - 1));
            int j  = (int)(idx & (L - 1));
            int nn = sh_lens[bb];
            if (i < nn && j < nn) {
                float x = __ldg(&ph_all[idx]);
                f1 += fmaxf(x, 0.f) + log1pf(__expf(-fabsf(x))) - x * (float)__ldg(&phind_all[idx]);
                float y = __ldg(&pt_all[idx]);
                f2 += fmaxf(y, 0.f) + log1pf(__expf(-fabsf(y))) - y * (float)__ldg(&ptind_all[idx]);
            }
        }
        #pragma unroll
        for (int o = 16; o; o >>= 1) {
            f1 += __shfl_down_sync(0xffffffffu, f1, o);
            f2 += __shfl_down_sync(0xffffffffu, f2, o);
        }
        if (lane == 0) sh_red[wid] = (double)f1;
        __syncthreads();
        if (wid == 0) {
            double v = (lane < NW) ? sh_red[lane] : 0.0;
            #pragma unroll
            for (int o = 8; o; o >>= 1) v += __shfl_down_sync(0xffffffffu, v, o);
            if (lane == 0) g_bce1[c] = v;
        }
        __syncthreads();
        if (lane == 0) sh_red[wid] = (double)f2;
        __syncthreads();
        if (wid == 0) {
            double v = (lane < NW) ? sh_red[lane] : 0.0;
            #pragma unroll
            for (int o = 8; o; o >>= 1) v += __shfl_down_sync(0xffffffffu, v, o);
            if (lane == 0) g_bce2[c] = v;
        }
        __syncthreads();
    }

    // ============ arrival protocol: last CTA computes the final scalar ============
    if (tid == 0) {
        __threadfence();
        unsigned long long old = atomicAdd(&g_ctr, 1ULL);
        if ((old % (unsigned long long)NCTA) == (unsigned long long)(NCTA - 1)) {
            __threadfence();
            double span = 0.0, b1 = 0.0, b2 = 0.0, lsum = 0.0, sq = 0.0;
            for (int bb = 0; bb < BB; ++bb) {
                span += *((volatile double*)&g_span[bb]);
                double nn = (double)(*((volatile int*)&g_lens[bb]));
                lsum += nn; sq += nn * nn;
            }
            for (int k = 0; k < NBCE; ++k) {
                b1 += *((volatile double*)&g_bce1[k]);
                b2 += *((volatile double*)&g_bce2[k]);
            }
            double loss_spans = -span / lsum;
            double loss = 0.1 * loss_spans + 0.9 * (b1 / sq + b2 / sq);
            out[0] = (float)loss;
        }
    }
}

extern "C" void kernel_launch(void* const* d_in, const int* in_sizes, int n_in,
                              void* d_out, int out_size) {
    const float* span_logits = (const float*)d_in[0];
    const float* ph          = (const float*)d_in[1];
    const float* pt          = (const float*)d_in[2];
    const float* ph_arc      = (const float*)d_in[3];
    const int*   spans_ind   = (const int*)d_in[4];
    const int*   ph_ind      = (const int*)d_in[5];
    const int*   pt_ind      = (const int*)d_in[6];
    const unsigned char* maskspan = (const unsigned char*)d_in[8];

    (void)in_sizes; (void)n_in; (void)out_size;

    cudaFuncSetAttribute(main_kernel, cudaFuncAttributeMaxDynamicSharedMemorySize,
                         SMEM_BYTES);

    main_kernel<<<NCTA, TMAIN, SMEM_BYTES>>>(span_logits, ph, pt, ph_arc,
                                             spans_ind, ph_ind, pt_ind, maskspan,
                                             (float*)d_out);
}

// round 8
// speedup vs baseline: 2.5763x; 2.5763x over previous
#include <cuda_runtime.h>
#include <cstdint>

#define L 256
#define BB 16
#define NC 8
#define LL2 (L * L)
#define NEGF (-1000000000.0f)
#define TMAIN 1024
#define NW 32                      // warps per CTA
#define NCTA (BB * NC)             // 128
#define WT 6000                    // lane-term threshold: partitioned vs redundant

// -------- device scratch (no allocations allowed) --------
__device__ float  g_bS[BB * LL2];  // beta start-major: bS[i*L+w] = beta(i, i+w)
__device__ float  g_bE[BB * LL2];  // beta end-major:   bE[j*L+w] = beta(j-w, j)
__device__ float  g_gS[BB * LL2];  // gamma=alpha+lg start-major
__device__ float  g_gE[BB * LL2];  // gamma end-major
__device__ int    g_lens[BB];
__device__ double g_span[NCTA];
__device__ double g_b1[NCTA], g_b2[NCTA];
__device__ unsigned long long g_ctr;

// hardware cluster barrier — correct by construction (all threads participate)
#define CLUSTER_SYNC() do { \
    asm volatile("barrier.cluster.arrive.aligned;" ::: "memory"); \
    asm volatile("barrier.cluster.wait.aligned;"   ::: "memory"); } while (0)

// two-phase warp LSE over T terms; returns m+log(sum) valid in lane 0
template<int NCH, class F>
__device__ __forceinline__ float warp_lse(int T, int lane, F f) {
    float vv[NCH];
    float m = NEGF;
    #pragma unroll
    for (int k = 0; k < NCH; ++k) {
        int t = lane + k * 32;
        vv[k] = (t < T) ? f(t) : NEGF;
        m = fmaxf(m, vv[k]);
    }
    #pragma unroll
    for (int o = 16; o; o >>= 1) m = fmaxf(m, __shfl_xor_sync(0xffffffffu, m, o));
    float s = 0.f;
    #pragma unroll
    for (int k = 0; k < NCH; ++k) s += __expf(vv[k] - m);   // NEGF terms underflow to 0
    #pragma unroll
    for (int o = 16; o; o >>= 1) s += __shfl_xor_sync(0xffffffffu, s, o);
    return m + __logf(s);
}

__device__ __forceinline__ int robust_len(const unsigned char* __restrict__ maskspan,
                                          int b, int lane) {
    const unsigned char* rowb = maskspan + (size_t)b * LL2;
    int c8 = 0;
    for (int j = lane; j < L; j += 32) c8 += (rowb[j] != 0) ? 1 : 0;
    #pragma unroll
    for (int o = 16; o; o >>= 1) c8 += __shfl_xor_sync(0xffffffffu, c8, o);
    int n;
    if (c8 >= 100 && rowb[0] == 1) {
        n = c8;
    } else {
        const unsigned int* rowi = ((const unsigned int*)maskspan) + (size_t)b * LL2;
        int c32 = 0;
        for (int j = lane; j < L; j += 32) c32 += (rowi[j] != 0u) ? 1 : 0;
        #pragma unroll
        for (int o = 16; o; o >>= 1) c32 += __shfl_xor_sync(0xffffffffu, c32, o);
        n = c32;
    }
    return max(1, min(L, n));
}

__global__ void __launch_bounds__(TMAIN, 1)
main_kernel(const float* __restrict__ lg_all,
            const float* __restrict__ ph_all,  const float* __restrict__ pt_all,
            const float* __restrict__ pharc_all,
            const int* __restrict__ spans_all,
            const int* __restrict__ phind_all, const int* __restrict__ ptind_all,
            const unsigned char* __restrict__ maskspan,
            float* __restrict__ out) {
    __shared__ double sh_red[NW];
    __shared__ int    sh_n;
    __shared__ int    sh_last;

    const int cb   = blockIdx.x;
    const int b    = cb >> 3;
    const int rank = cb & 7;
    const int tid  = threadIdx.x;
    const int lane = tid & 31;
    const int wid  = tid >> 5;
    const int gw   = rank * NW + wid;          // global warp id in cluster [0,256)

    // ---- lens ----
    if (wid == 0) {
        int n = robust_len(maskspan, b, lane);
        if (lane == 0) { sh_n = n; if (rank == 0) g_lens[b] = n; }
    }
    __syncthreads();
    const int n = sh_n;

    const float* __restrict__ lg    = lg_all    + (size_t)b * LL2;
    const float* __restrict__ pharc = pharc_all + (size_t)b * LL2;
    const int*   __restrict__ spans = spans_all + (size_t)b * LL2;
    float* __restrict__ bS = g_bS + (size_t)b * LL2;
    float* __restrict__ bE = g_bE + (size_t)b * LL2;
    float* __restrict__ gS = g_gS + (size_t)b * LL2;
    float* __restrict__ gE = g_gE + (size_t)b * LL2;

    // ---- width 0 (redundant: every CTA writes identical values) ----
    for (int i = tid; i < n; i += TMAIN) {
        float v = __ldg(&lg[i * L + i]);
        __stcg(&bS[i * L], v);
        __stcg(&bE[i * L], v);
    }
    __syncthreads();

    // ================= inside, widths 1..n-1 =================
    for (int w = 1; w < n; ++w) {
        const int ncells = n - w;
        const bool part = (ncells * w > WT);
        if (part) {
            for (int i = gw; i < ncells; i += NC * NW) {
                const float* Lr = bS + i * L;
                const float* Rr = bE + (i + w) * L + (w - 1);
                auto f = [&](int t) { return __ldcg(Lr + t) + __ldcg(Rr - t); };
                float v;
                if      (w <= 32)  v = warp_lse<1>(w, lane, f);
                else if (w <= 128) v = warp_lse<4>(w, lane, f);
                else               v = warp_lse<8>(w, lane, f);
                if (lane == 0) {
                    float res = v + __ldg(&lg[i * L + i + w]);
                    __stcg(&bS[i * L + w], res);
                    __stcg(&bE[(i + w) * L + w], res);
                }
            }
            CLUSTER_SYNC();
        } else if (w <= 8) {
            for (int i = tid; i < ncells; i += TMAIN) {
                const float* Lr = bS + i * L;
                const float* Rr = bE + (i + w) * L;
                float vv[8]; float m = NEGF;
                #pragma unroll
                for (int k = 0; k < 8; ++k)
                    if (k < w) { vv[k] = __ldcg(Lr + k) + __ldcg(Rr + (w - 1 - k)); m = fmaxf(m, vv[k]); }
                float s = 0.f;
                #pragma unroll
                for (int k = 0; k < 8; ++k) if (k < w) s += __expf(vv[k] - m);
                float res = m + __logf(s) + __ldg(&lg[i * L + i + w]);
                __stcg(&bS[i * L + w], res);
                __stcg(&bE[(i + w) * L + w], res);
            }
            __syncthreads();
        } else {
            for (int i = wid; i < ncells; i += NW) {
                const float* Lr = bS + i * L;
                const float* Rr = bE + (i + w) * L + (w - 1);
                auto f = [&](int t) { return __ldcg(Lr + t) + __ldcg(Rr - t); };
                float v;
                if      (w <= 32)  v = warp_lse<1>(w, lane, f);
                else if (w <= 128) v = warp_lse<4>(w, lane, f);
                else               v = warp_lse<8>(w, lane, f);
                if (lane == 0) {
                    float res = v + __ldg(&lg[i * L + i + w]);
                    __stcg(&bS[i * L + w], res);
                    __stcg(&bE[(i + w) * L + w], res);
                }
            }
            __syncthreads();
        }
    }

    const float logZ = __ldcg(&bS[0 * L + (n - 1)]);
    double acc = 0.0;

    // ---- outside root (w = n-1): alpha = 0, mu = 1 (redundant; rank0 counts) ----
    if (tid == 0) {
        float lgv = __ldg(&lg[0 * L + (n - 1)]);
        __stcg(&gS[0 * L + (n - 1)], lgv);
        __stcg(&gE[(n - 1) * L + (n - 1)], lgv);
        if (rank == 0) {
            float p = 1.f / (1.f + __expf(-__ldg(&pharc[n - 1])));
            acc += (__ldg(&spans[n - 1]) >= 2) ? (double)__logf(p) : (double)log1pf(-p);
        }
    }
    __syncthreads();

    // ================= outside, widths n-2..0 (loss fused) =================
    for (int w = n - 2; w >= 0; --w) {
        const int ncells = n - w;
        const int T0 = n - 1 - w;
        const bool part = (ncells * T0 > WT);
        const int start = part ? gw : wid;
        const int step  = part ? (NC * NW) : NW;
        for (int a = start; a < ncells; a += step) {
            const int bj = a + w;
            const int c1 = n - 1 - bj;
            const float* gSr = gS + a * L + (w + 1);        // [t]
            const float* bSr = bS + (bj + 1) * L;           // [t]
            const float* gEr = gE + bj * L + bj;            // [-ii]
            const float* bEr = bE + (a - 1) * L + (a - 1);  // [-ii]
            auto f = [&](int t) {
                if (t < c1) return __ldcg(gSr + t) + __ldcg(bSr + t);
                int ii = t - c1;
                return __ldcg(gEr - ii) + __ldcg(bEr - ii);
            };
            float al;
            if      (T0 <= 32)  al = warp_lse<1>(T0, lane, f);
            else if (T0 <= 128) al = warp_lse<4>(T0, lane, f);
            else                al = warp_lse<8>(T0, lane, f);
            if (lane == 0) {
                float lgv = __ldg(&lg[a * L + bj]);
                __stcg(&gS[a * L + w], al + lgv);
                __stcg(&gE[bj * L + w], al + lgv);
                if (part || rank == 0) {
                    float mu = fminf(__expf(al + __ldcg(&bS[a * L + w]) - logZ), 1.0f);
                    float p  = 1.f / (1.f + __expf(-__ldg(&pharc[a * L + bj])));
                    float pm = p * mu;
                    acc += (__ldg(&spans[a * L + bj]) >= 2) ? (double)__logf(pm)
                                                            : (double)log1pf(-pm);
                }
            }
        }
        if (part) CLUSTER_SYNC();
        else      __syncthreads();
    }

    // ================= BCE slice (batch b, partitioned across the 8 CTAs) ==========
    float f1 = 0.f, f2 = 0.f;
    {
        const float* __restrict__ ph    = ph_all    + (size_t)b * LL2;
        const float* __restrict__ pt    = pt_all    + (size_t)b * LL2;
        const int*   __restrict__ phind = phind_all + (size_t)b * LL2;
        const int*   __restrict__ ptind = ptind_all + (size_t)b * LL2;
        for (int idx = rank * TMAIN + tid; idx < n * L; idx += NC * TMAIN) {
            int j = idx & (L - 1);
            if (j < n) {
                float x = __ldg(&ph[idx]);
                f1 += fmaxf(x, 0.f) + log1pf(__expf(-fabsf(x))) - x * (float)__ldg(&phind[idx]);
                float y = __ldg(&pt[idx]);
                f2 += fmaxf(y, 0.f) + log1pf(__expf(-fabsf(y))) - y * (float)__ldg(&ptind[idx]);
            }
        }
    }

    // ---- per-CTA reductions into slots ----
    #pragma unroll
    for (int o = 16; o; o >>= 1) {
        acc += __shfl_down_sync(0xffffffffu, acc, o);
        f1  += __shfl_down_sync(0xffffffffu, f1, o);
        f2  += __shfl_down_sync(0xffffffffu, f2, o);
    }
    if (lane == 0) sh_red[wid] = acc;
    __syncthreads();
    if (wid == 0) {
        double v = sh_red[lane];
        #pragma unroll
        for (int o = 16; o; o >>= 1) v += __shfl_down_sync(0xffffffffu, v, o);
        if (lane == 0) g_span[cb] = v;
    }
    __syncthreads();
    if (lane == 0) sh_red[wid] = (double)f1;
    __syncthreads();
    if (wid == 0) {
        double v = sh_red[lane];
        #pragma unroll
        for (int o = 16; o; o >>= 1) v += __shfl_down_sync(0xffffffffu, v, o);
        if (lane == 0) g_b1[cb] = v;
    }
    __syncthreads();
    if (lane == 0) sh_red[wid] = (double)f2;
    __syncthreads();
    if (wid == 0) {
        double v = sh_red[lane];
        #pragma unroll
        for (int o = 16; o; o >>= 1) v += __shfl_down_sync(0xffffffffu, v, o);
        if (lane == 0) g_b2[cb] = v;
    }
    __syncthreads();

    // ================= arrival protocol: last CTA finalizes =================
    if (tid == 0) {
        __threadfence();
        unsigned long long old = atomicAdd(&g_ctr, 1ULL);
        sh_last = ((old % (unsigned long long)NCTA) == (unsigned long long)(NCTA - 1)) ? 1 : 0;
        if (sh_last) __threadfence();
    }
    __syncthreads();
    if (sh_last && wid == 0) {
        double span = 0.0, b1 = 0.0, b2 = 0.0;
        for (int k = lane; k < NCTA; k += 32) {
            span += *((volatile double*)&g_span[k]);
            b1   += *((volatile double*)&g_b1[k]);
            b2   += *((volatile double*)&g_b2[k]);
        }
        #pragma unroll
        for (int o = 16; o; o >>= 1) {
            span += __shfl_down_sync(0xffffffffu, span, o);
            b1   += __shfl_down_sync(0xffffffffu, b1, o);
            b2   += __shfl_down_sync(0xffffffffu, b2, o);
        }
        if (lane == 0) {
            double lsum = 0.0, sq = 0.0;
            for (int bb = 0; bb < BB; ++bb) {
                double nn = (double)(*((volatile int*)&g_lens[bb]));
                lsum += nn; sq += nn * nn;
            }
            double loss_spans = -span / lsum;
            double loss = 0.1 * loss_spans + 0.9 * (b1 / sq + b2 / sq);
            out[0] = (float)loss;
        }
    }
}

extern "C" void kernel_launch(void* const* d_in, const int* in_sizes, int n_in,
                              void* d_out, int out_size) {
    const float* span_logits = (const float*)d_in[0];
    const float* ph          = (const float*)d_in[1];
    const float* pt          = (const float*)d_in[2];
    const float* ph_arc      = (const float*)d_in[3];
    const int*   spans_ind   = (const int*)d_in[4];
    const int*   ph_ind      = (const int*)d_in[5];
    const int*   pt_ind      = (const int*)d_in[6];
    const unsigned char* maskspan = (const unsigned char*)d_in[8];

    (void)in_sizes; (void)n_in; (void)out_size;

    cudaLaunchConfig_t cfg = {};
    cfg.gridDim  = dim3(NCTA, 1, 1);
    cfg.blockDim = dim3(TMAIN, 1, 1);
    cfg.dynamicSmemBytes = 0;
    cfg.stream = 0;
    cudaLaunchAttribute attrs[1];
    attrs[0].id = cudaLaunchAttributeClusterDimension;
    attrs[0].val.clusterDim.x = NC;
    attrs[0].val.clusterDim.y = 1;
    attrs[0].val.clusterDim.z = 1;
    cfg.attrs = attrs;
    cfg.numAttrs = 1;
    cudaLaunchKernelEx(&cfg, main_kernel,
                       span_logits, ph, pt, ph_arc, spans_ind, ph_ind, pt_ind, maskspan,
                       (float*)d_out);
}